// round 6
// baseline (speedup 1.0000x reference)
#include <cuda_runtime.h>
#include <cuda_fp16.h>

#define XD 256
#define HD 2048
#define YD 256
#define TT 4096
#define GRID 128
#define NTH 256
#define COLS 16   // hidden columns per CTA per matrix (128*16 = 2048)

#define SMEM_SEQ (48 * 1024 * (int)sizeof(__half2) + 2 * HD * (int)sizeof(float) + HD * (int)sizeof(float))

// ------------------------------------------------------------------
// Device-global scratch (no cudaMalloc allowed)
// ------------------------------------------------------------------
__device__ float g_pre[(size_t)TT * 3 * HD];            // [t][m][j], m: 0=u,1=r,2=c (x-part + bias)
__device__ __align__(16) float g_h[2][HD];              // ping-pong hidden state
__device__ __align__(16) float g_hr[HD];                // h * Lr
__device__ int g_flagA[GRID];                           // B1 arrival flags (generation = t+1)
__device__ int g_flagB[GRID];                           // B2 arrival flags

// ------------------------------------------------------------------
// Init: reset flags, load h0
// ------------------------------------------------------------------
__global__ void init_kernel(const float* __restrict__ h0) {
    int i = blockIdx.x * blockDim.x + threadIdx.x;
    if (i < HD) g_h[0][i] = h0[i];
    if (i < GRID) { g_flagA[i] = 0; g_flagB[i] = 0; }
}

// ------------------------------------------------------------------
// Precompute: g_pre[t, m, j] = x[t] @ Wm[0:256, :] + bm   (parallel GEMM)
// grid = (HD/64, TT/64, 3), 256 threads
// ------------------------------------------------------------------
__global__ void __launch_bounds__(256) pre_gemm(
    const float* __restrict__ x,
    const float* __restrict__ Wu, const float* __restrict__ Wr, const float* __restrict__ Wc,
    const float* __restrict__ bu, const float* __restrict__ br, const float* __restrict__ bc)
{
    const int z = blockIdx.z;
    const float* __restrict__ W    = (z == 0) ? Wu : ((z == 1) ? Wr : Wc);
    const float* __restrict__ bias = (z == 0) ? bu : ((z == 1) ? br : bc);

    __shared__ __align__(16) float As[64][16];
    __shared__ __align__(16) float Bs[16][64];

    const int tid = threadIdx.x;
    const int tx = tid & 15;
    const int ty = tid >> 4;
    const int row0 = blockIdx.y * 64;
    const int col0 = blockIdx.x * 64;

    float acc[4][4];
#pragma unroll
    for (int i = 0; i < 4; i++)
#pragma unroll
        for (int j = 0; j < 4; j++) acc[i][j] = 0.f;

    for (int k0 = 0; k0 < XD; k0 += 16) {
#pragma unroll
        for (int l = 0; l < 4; l++) {
            int idx = tid + l * 256;
            int kk = idx & 15, r = idx >> 4;
            As[r][kk] = x[(size_t)(row0 + r) * XD + k0 + kk];
        }
#pragma unroll
        for (int l = 0; l < 4; l++) {
            int idx = tid + l * 256;
            int c = idx & 63, kk = idx >> 6;
            Bs[kk][c] = W[(size_t)(k0 + kk) * HD + col0 + c];
        }
        __syncthreads();
#pragma unroll
        for (int kk = 0; kk < 16; kk++) {
            float a[4];
#pragma unroll
            for (int i = 0; i < 4; i++) a[i] = As[ty * 4 + i][kk];
            float4 b4 = ((const float4*)&Bs[kk][0])[tx];
            float b[4] = {b4.x, b4.y, b4.z, b4.w};
#pragma unroll
            for (int i = 0; i < 4; i++)
#pragma unroll
                for (int j = 0; j < 4; j++)
                    acc[i][j] = fmaf(a[i], b[j], acc[i][j]);
        }
        __syncthreads();
    }

#pragma unroll
    for (int i = 0; i < 4; i++) {
        int t = row0 + ty * 4 + i;
#pragma unroll
        for (int j = 0; j < 4; j++) {
            int c = col0 + tx * 4 + j;
            g_pre[(size_t)t * (3 * HD) + (size_t)z * HD + c] = acc[i][j] + bias[c];
        }
    }
}

// ------------------------------------------------------------------
// Helpers
// ------------------------------------------------------------------
__device__ __forceinline__ float warp_sum(float v) {
#pragma unroll
    for (int o = 16; o; o >>= 1) v += __shfl_xor_sync(0xffffffffu, v, o);
    return v;
}

__device__ __forceinline__ float sigmoidf_(float v) { return 1.f / (1.f + expf(-v)); }

__device__ __forceinline__ void st_rel(int* p, int v) {
    asm volatile("st.release.gpu.global.b32 [%0], %1;" :: "l"(p), "r"(v) : "memory");
}
__device__ __forceinline__ int ld_acq(const int* p) {
    int v;
    asm volatile("ld.acquire.gpu.global.b32 %0, [%1];" : "=r"(v) : "l"(p) : "memory");
    return v;
}

// Two 2048-long dot products against fp16 weight columns in smem.
// Column j stored as half2[1024]; half2 index (k*32+lane) = rows (64k+2*lane, 64k+2*lane+1)
// matching hreg[k] = (h[64k+2*lane], h[64k+2*lane+1]).
__device__ __forceinline__ void dot2_h(const __half2* __restrict__ w0,
                                       const __half2* __restrict__ w1,
                                       const float2* hreg, int lane,
                                       float& r0, float& r1) {
    float a0 = 0.f, a1 = 0.f, b0 = 0.f, b1 = 0.f;
#pragma unroll
    for (int k = 0; k < 32; k++) {
        float2 hv = hreg[k];
        float2 x0 = __half22float2(w0[k * 32 + lane]);
        float2 x1 = __half22float2(w1[k * 32 + lane]);
        a0 = fmaf(x0.x, hv.x, a0); a1 = fmaf(x0.y, hv.y, a1);
        b0 = fmaf(x1.x, hv.x, b0); b1 = fmaf(x1.y, hv.y, b1);
    }
    r0 = warp_sum(a0 + a1);
    r1 = warp_sum(b0 + b1);
}

__device__ __forceinline__ float dot_y(const float2* __restrict__ wy,
                                       const float2* hreg, int lane) {
    float a0 = 0.f, a1 = 0.f;
#pragma unroll
    for (int k = 0; k < 32; k++) {
        float2 hv = hreg[k];
        float2 wv = wy[k * 32 + lane];
        a0 = fmaf(wv.x, hv.x, a0); a1 = fmaf(wv.y, hv.y, a1);
    }
    return warp_sum(a0 + a1);
}

// ------------------------------------------------------------------
// Persistent sequential kernel: 128 co-resident CTAs (1/SM).
// Distributed flag barriers with fused poll-and-stage.
// ------------------------------------------------------------------
__global__ void __launch_bounds__(NTH, 1) gru_seq(
    const float* __restrict__ Wu, const float* __restrict__ Wr, const float* __restrict__ Wc,
    const float* __restrict__ Why, const float* __restrict__ by,
    float* __restrict__ out, int out_size)
{
    extern __shared__ char sm[];
    __half2* wS  = (__half2*)sm;                                 // 48 cols * 1024 half2
    float*   wyS = (float*)(sm + 48 * 1024 * sizeof(__half2));   // 2 y-cols fp32
    float*   hS  = wyS + 2 * HD;                                 // staged h / hr

    const int tid  = threadIdx.x;
    const int lane = tid & 31;
    const int w    = tid >> 5;         // warp id, 8 warps
    const int cta  = blockIdx.x;
    const int colBase = cta * COLS;

    // ---- one-time: stage h-part weights into smem as fp16 ----
#pragma unroll 1
    for (int m = 0; m < 3; m++) {
        const float* __restrict__ Wm =
            ((m == 0) ? Wu : ((m == 1) ? Wr : Wc)) + (size_t)XD * HD;  // skip x rows
        __half* dst = (__half*)(wS + (size_t)m * COLS * (HD / 2));
        for (int idx = tid; idx < COLS * HD; idx += NTH) {
            int cl  = idx & (COLS - 1);
            int row = idx >> 4;
            dst[(size_t)cl * HD + row] = __float2half_rn(Wm[(size_t)row * HD + colBase + cl]);
        }
    }
    // y columns fp32: global y cols {2*cta, 2*cta+1}
    for (int idx = tid; idx < 2 * HD; idx += NTH) {
        int c = idx & 1, row = idx >> 1;
        wyS[c * HD + row] = Why[(size_t)row * YD + cta * 2 + c];
    }

    const int c0 = 2 * w, c1 = c0 + 1;
    const int j0 = colBase + c0, j1 = colBase + c1;
    const __half2* wU0 = wS + (size_t)(0 * COLS + c0) * (HD / 2);
    const __half2* wU1 = wS + (size_t)(0 * COLS + c1) * (HD / 2);
    const __half2* wR0 = wS + (size_t)(1 * COLS + c0) * (HD / 2);
    const __half2* wR1 = wS + (size_t)(1 * COLS + c1) * (HD / 2);
    const __half2* wC0 = wS + (size_t)(2 * COLS + c0) * (HD / 2);
    const __half2* wC1 = wS + (size_t)(2 * COLS + c1) * (HD / 2);
    const float2*  wy  = (const float2*)(wyS + (w < 2 ? w : 0) * HD);
    const float    yb  = (w < 2) ? by[cta * 2 + w] : 0.f;

    // ---- prologue: stage initial h, prefetch pre[0] ----
    for (int i = tid * 4; i < HD; i += NTH * 4)
        ((float4*)hS)[i >> 2] = __ldcg((const float4*)&g_h[0][i]);
    float2 pu = __ldcg((const float2*)&g_pre[0 * HD + j0]);
    float2 pr = __ldcg((const float2*)&g_pre[1 * HD + j0]);
    float2 pc = __ldcg((const float2*)&g_pre[2 * HD + j0]);
    __syncthreads();

    float2 hreg[32], hreg2[32];

    for (int t = 0; t < TT; t++) {
        const int nxt = (t & 1) ^ 1;

        // h -> registers (hS holds s_t)
#pragma unroll
        for (int k = 0; k < 32; k++) hreg[k] = ((const float2*)hS)[k * 32 + lane];
        if (w < 2) {
#pragma unroll
            for (int k = 0; k < 32; k++) hreg2[k] = hreg[k];
        }
        const float hold0 = hS[j0], hold1 = hS[j1];

        // ---- reset gate, publish h*Lr ----
        float r0, r1;
        dot2_h(wR0, wR1, hreg, lane, r0, r1);
        r0 = sigmoidf_(r0 + pr.x);
        r1 = sigmoidf_(r1 + pr.y);
        if (lane == 0)
            __stcg((float2*)&g_hr[j0], make_float2(hold0 * r0, hold1 * r1));
        __syncthreads();
        if (tid == 0) { __threadfence(); st_rel(&g_flagA[cta], t + 1); }   // B1 arrive

        // ---- B1 shadow: update gate (independent of hr) ----
        float u0, u1;
        dot2_h(wU0, wU1, hreg, lane, u0, u1);
        u0 = sigmoidf_(u0 + pu.x);
        u1 = sigmoidf_(u1 + pu.y);

        // ---- B1 wait + fused stage of hr ----
        if (tid < GRID) {
            while (ld_acq(&g_flagA[tid]) < t + 1) { }
            const float4* src = (const float4*)&g_hr[tid * 16];
            float4* dst = (float4*)&hS[tid * 16];
            dst[0] = __ldcg(src + 0); dst[1] = __ldcg(src + 1);
            dst[2] = __ldcg(src + 2); dst[3] = __ldcg(src + 3);
        }
        __syncthreads();

        // ---- candidate + new h ----
#pragma unroll
        for (int k = 0; k < 32; k++) hreg[k] = ((const float2*)hS)[k * 32 + lane];
        float cc0, cc1;
        dot2_h(wC0, wC1, hreg, lane, cc0, cc1);
        cc0 = tanhf(cc0 + pc.x);
        cc1 = tanhf(cc1 + pc.y);
        const float hn0 = cc0 * u0 + hold0 * (1.f - u0);
        const float hn1 = cc1 * u1 + hold1 * (1.f - u1);
        if (lane == 0)
            __stcg((float2*)&g_h[nxt][j0], make_float2(hn0, hn1));
        __syncthreads();
        if (tid == 0) { __threadfence(); st_rel(&g_flagB[cta], t + 1); }   // B2 arrive

        // ---- B2 shadow: y[t-1] from s_t (register copy) + pre prefetch ----
        if (w < 2 && t > 0) {
            float yv = dot_y(wy, hreg2, lane) + yb;
            if (lane == 0) out[(size_t)(t - 1) * YD + cta * 2 + w] = yv;
        }
        if (t + 1 < TT) {
            const float* pn = g_pre + (size_t)(t + 1) * (3 * HD);
            pu = __ldcg((const float2*)&pn[0 * HD + j0]);
            pr = __ldcg((const float2*)&pn[1 * HD + j0]);
            pc = __ldcg((const float2*)&pn[2 * HD + j0]);
        }

        // ---- B2 wait + fused stage of s_{t+1} ----
        if (tid < GRID) {
            while (ld_acq(&g_flagB[tid]) < t + 1) { }
            const float4* src = (const float4*)&g_h[nxt][tid * 16];
            float4* dst = (float4*)&hS[tid * 16];
            dst[0] = __ldcg(src + 0); dst[1] = __ldcg(src + 1);
            dst[2] = __ldcg(src + 2); dst[3] = __ldcg(src + 3);
        }
        __syncthreads();
    }

    // ---- epilogue: hS = s_TT. y[TT-1] and h_fin ----
    if (w < 2) {
#pragma unroll
        for (int k = 0; k < 32; k++) hreg[k] = ((const float2*)hS)[k * 32 + lane];
        float yv = dot_y(wy, hreg, lane) + yb;
        if (lane == 0) out[(size_t)(TT - 1) * YD + cta * 2 + w] = yv;
    }
    if (cta == 0 && out_size >= TT * YD + HD) {
        for (int i = tid; i < HD; i += NTH) out[(size_t)TT * YD + i] = hS[i];
    }
}

// ------------------------------------------------------------------
// Launch
// ------------------------------------------------------------------
extern "C" void kernel_launch(void* const* d_in, const int* in_sizes, int n_in,
                              void* d_out, int out_size) {
    const float* x   = (const float*)d_in[0];
    const float* h0  = (const float*)d_in[1];
    const float* Wc  = (const float*)d_in[2];
    const float* Wu  = (const float*)d_in[3];
    const float* Wr  = (const float*)d_in[4];
    const float* bc  = (const float*)d_in[5];
    const float* bu  = (const float*)d_in[6];
    const float* br  = (const float*)d_in[7];
    const float* Why = (const float*)d_in[8];
    const float* by  = (const float*)d_in[9];
    float* out = (float*)d_out;

    cudaFuncSetAttribute(gru_seq, cudaFuncAttributeMaxDynamicSharedMemorySize, SMEM_SEQ);

    init_kernel<<<8, 256>>>(h0);

    dim3 g(HD / 64, TT / 64, 3);
    pre_gemm<<<g, 256>>>(x, Wu, Wr, Wc, bu, br, bc);

    gru_seq<<<GRID, NTH, SMEM_SEQ>>>(Wu, Wr, Wc, Why, by, out, out_size);
}

// round 7
// speedup vs baseline: 2.1373x; 2.1373x over previous
#include <cuda_runtime.h>
#include <cuda_fp16.h>

#define XD 256
#define HD 2048
#define YD 256
#define TT 4096
#define GRID 128
#define NTH 288          // 8 compute warps + 1 sync warp
#define COLS 16          // hidden columns per CTA per matrix (128*16 = 2048)

#define SMEM_SEQ (48 * 1024 * (int)sizeof(__half2) + 2 * HD * (int)sizeof(float) + HD * (int)sizeof(float))

// ------------------------------------------------------------------
// Device-global scratch (no cudaMalloc allowed)
// ------------------------------------------------------------------
__device__ float g_pre[(size_t)TT * 3 * HD];            // [t][m][j], m: 0=u,1=r,2=c (x-part + bias)
__device__ __align__(16) float g_h[2][HD];              // ping-pong hidden state
__device__ __align__(16) float g_hr[HD];                // h * Lr
__device__ unsigned g_cnt;                              // monotonic barrier counter

// ------------------------------------------------------------------
// Init: reset counter, load h0
// ------------------------------------------------------------------
__global__ void init_kernel(const float* __restrict__ h0) {
    int i = blockIdx.x * blockDim.x + threadIdx.x;
    if (i < HD) g_h[0][i] = h0[i];
    if (i == 0) g_cnt = 0u;
}

// ------------------------------------------------------------------
// Precompute: g_pre[t, m, j] = x[t] @ Wm[0:256, :] + bm   (parallel GEMM)
// grid = (HD/64, TT/64, 3), 256 threads
// ------------------------------------------------------------------
__global__ void __launch_bounds__(256) pre_gemm(
    const float* __restrict__ x,
    const float* __restrict__ Wu, const float* __restrict__ Wr, const float* __restrict__ Wc,
    const float* __restrict__ bu, const float* __restrict__ br, const float* __restrict__ bc)
{
    const int z = blockIdx.z;
    const float* __restrict__ W    = (z == 0) ? Wu : ((z == 1) ? Wr : Wc);
    const float* __restrict__ bias = (z == 0) ? bu : ((z == 1) ? br : bc);

    __shared__ __align__(16) float As[64][16];
    __shared__ __align__(16) float Bs[16][64];

    const int tid = threadIdx.x;
    const int tx = tid & 15;
    const int ty = tid >> 4;
    const int row0 = blockIdx.y * 64;
    const int col0 = blockIdx.x * 64;

    float acc[4][4];
#pragma unroll
    for (int i = 0; i < 4; i++)
#pragma unroll
        for (int j = 0; j < 4; j++) acc[i][j] = 0.f;

    for (int k0 = 0; k0 < XD; k0 += 16) {
#pragma unroll
        for (int l = 0; l < 4; l++) {
            int idx = tid + l * 256;
            int kk = idx & 15, r = idx >> 4;
            As[r][kk] = x[(size_t)(row0 + r) * XD + k0 + kk];
        }
#pragma unroll
        for (int l = 0; l < 4; l++) {
            int idx = tid + l * 256;
            int c = idx & 63, kk = idx >> 6;
            Bs[kk][c] = W[(size_t)(k0 + kk) * HD + col0 + c];
        }
        __syncthreads();
#pragma unroll
        for (int kk = 0; kk < 16; kk++) {
            float a[4];
#pragma unroll
            for (int i = 0; i < 4; i++) a[i] = As[ty * 4 + i][kk];
            float4 b4 = ((const float4*)&Bs[kk][0])[tx];
            float b[4] = {b4.x, b4.y, b4.z, b4.w};
#pragma unroll
            for (int i = 0; i < 4; i++)
#pragma unroll
                for (int j = 0; j < 4; j++)
                    acc[i][j] = fmaf(a[i], b[j], acc[i][j]);
        }
        __syncthreads();
    }

#pragma unroll
    for (int i = 0; i < 4; i++) {
        int t = row0 + ty * 4 + i;
#pragma unroll
        for (int j = 0; j < 4; j++) {
            int c = col0 + tx * 4 + j;
            g_pre[(size_t)t * (3 * HD) + (size_t)z * HD + c] = acc[i][j] + bias[c];
        }
    }
}

// ------------------------------------------------------------------
// Helpers
// ------------------------------------------------------------------
__device__ __forceinline__ float warp_sum(float v) {
#pragma unroll
    for (int o = 16; o; o >>= 1) v += __shfl_xor_sync(0xffffffffu, v, o);
    return v;
}

__device__ __forceinline__ float sigmoidf_(float v) { return 1.f / (1.f + expf(-v)); }

// Two 2048-long dot products against fp16 weight columns in smem.
// Column j stored as half2[1024]; half2 index (k*32+lane) = rows (64k+2*lane, 64k+2*lane+1)
// matching hreg[k] = (h[64k+2*lane], h[64k+2*lane+1]).
__device__ __forceinline__ void dot2_h(const __half2* __restrict__ w0,
                                       const __half2* __restrict__ w1,
                                       const float2* hreg, int lane,
                                       float& r0, float& r1) {
    float a0 = 0.f, a1 = 0.f, b0 = 0.f, b1 = 0.f;
#pragma unroll
    for (int k = 0; k < 32; k++) {
        float2 hv = hreg[k];
        float2 x0 = __half22float2(w0[k * 32 + lane]);
        float2 x1 = __half22float2(w1[k * 32 + lane]);
        a0 = fmaf(x0.x, hv.x, a0); a1 = fmaf(x0.y, hv.y, a1);
        b0 = fmaf(x1.x, hv.x, b0); b1 = fmaf(x1.y, hv.y, b1);
    }
    r0 = warp_sum(a0 + a1);
    r1 = warp_sum(b0 + b1);
}

__device__ __forceinline__ float dot_y(const float2* __restrict__ wy,
                                       const float2* hreg, int lane) {
    float a0 = 0.f, a1 = 0.f;
#pragma unroll
    for (int k = 0; k < 32; k++) {
        float2 hv = hreg[k];
        float2 wv = wy[k * 32 + lane];
        a0 = fmaf(wv.x, hv.x, a0); a1 = fmaf(wv.y, hv.y, a1);
    }
    return warp_sum(a0 + a1);
}

// ------------------------------------------------------------------
// Persistent sequential kernel: 128 co-resident CTAs (1/SM).
// Warps 0-7 compute; warp 8 handles global barrier + staging so the
// poll/stage latency overlaps the compute warps' shadow work.
// ------------------------------------------------------------------
__global__ void __launch_bounds__(NTH, 1) gru_seq(
    const float* __restrict__ Wu, const float* __restrict__ Wr, const float* __restrict__ Wc,
    const float* __restrict__ Why, const float* __restrict__ by,
    float* __restrict__ out, int out_size)
{
    extern __shared__ char sm[];
    __half2* wS  = (__half2*)sm;                                 // 48 cols * 1024 half2
    float*   wyS = (float*)(sm + 48 * 1024 * sizeof(__half2));   // 2 y-cols fp32
    float*   hS  = wyS + 2 * HD;                                 // staged h / hr

    const int tid  = threadIdx.x;
    const int lane = tid & 31;
    const int w    = tid >> 5;         // 0..8
    const bool comp = (w < 8);
    const int cta  = blockIdx.x;
    const int colBase = cta * COLS;

    // ---- one-time: stage h-part weights into smem as fp16 ----
#pragma unroll 1
    for (int m = 0; m < 3; m++) {
        const float* __restrict__ Wm =
            ((m == 0) ? Wu : ((m == 1) ? Wr : Wc)) + (size_t)XD * HD;  // skip x rows
        __half* dst = (__half*)(wS + (size_t)m * COLS * (HD / 2));
        for (int idx = tid; idx < COLS * HD; idx += NTH) {
            int cl  = idx & (COLS - 1);
            int row = idx >> 4;
            dst[(size_t)cl * HD + row] = __float2half_rn(Wm[(size_t)row * HD + colBase + cl]);
        }
    }
    // y columns fp32: global y cols {2*cta, 2*cta+1}
    for (int idx = tid; idx < 2 * HD; idx += NTH) {
        int c = idx & 1, row = idx >> 1;
        wyS[c * HD + row] = Why[(size_t)row * YD + cta * 2 + c];
    }

    const int c0 = comp ? 2 * w : 0, c1 = c0 + 1;
    const int j0 = colBase + c0, j1 = colBase + c1;
    const __half2* wU0 = wS + (size_t)(0 * COLS + c0) * (HD / 2);
    const __half2* wU1 = wS + (size_t)(0 * COLS + c1) * (HD / 2);
    const __half2* wR0 = wS + (size_t)(1 * COLS + c0) * (HD / 2);
    const __half2* wR1 = wS + (size_t)(1 * COLS + c1) * (HD / 2);
    const __half2* wC0 = wS + (size_t)(2 * COLS + c0) * (HD / 2);
    const __half2* wC1 = wS + (size_t)(2 * COLS + c1) * (HD / 2);
    const float2*  wy  = (const float2*)(wyS + (w < 2 ? w : 0) * HD);
    const float    yb  = (w < 2) ? by[cta * 2 + w] : 0.f;

    // ---- prologue: stage initial h (float4, all threads), prefetch pre[0] ----
    for (int idx = tid; idx < HD / 4; idx += NTH)
        ((float4*)hS)[idx] = __ldcg((const float4*)g_h[0] + idx);
    float2 pu = make_float2(0.f, 0.f), pr = pu, pc = pu;
    if (comp) {
        pu = __ldcg((const float2*)&g_pre[0 * HD + j0]);
        pr = __ldcg((const float2*)&g_pre[1 * HD + j0]);
        pc = __ldcg((const float2*)&g_pre[2 * HD + j0]);
    }
    __syncthreads();

    float2 hreg[32];

    for (int t = 0; t < TT; t++) {
        const int nxt = (t & 1) ^ 1;
        float hold0 = 0.f, hold1 = 0.f;
        float u0 = 0.f, u1 = 0.f;

        if (comp) {
            // hS holds s_t
#pragma unroll
            for (int k = 0; k < 32; k++) hreg[k] = ((const float2*)hS)[k * 32 + lane];
            hold0 = hS[j0]; hold1 = hS[j1];

            // ---- reset gate, publish h*Lr ----
            float r0, r1;
            dot2_h(wR0, wR1, hreg, lane, r0, r1);
            r0 = sigmoidf_(r0 + pr.x);
            r1 = sigmoidf_(r1 + pr.y);
            if (lane == 0)
                __stcg((float2*)&g_hr[j0], make_float2(hold0 * r0, hold1 * r1));
        }
        __syncthreads();   // S1: hr stores done; hS free for overwrite

        if (comp) {
            // ---- B1 shadow: update gate + y[t-1] (from hreg = h_t) ----
            dot2_h(wU0, wU1, hreg, lane, u0, u1);
            u0 = sigmoidf_(u0 + pu.x);
            u1 = sigmoidf_(u1 + pu.y);
            if (w < 2 && t > 0) {
                float yv = dot_y(wy, hreg, lane) + yb;
                if (lane == 0) out[(size_t)(t - 1) * YD + cta * 2 + w] = yv;
            }
        } else {
            // ---- sync warp: B1 arrive, poll, stage hr -> hS ----
            if (lane == 0) {
                __threadfence();
                atomicAdd(&g_cnt, 1u);
                unsigned tgt = (unsigned)(2 * t + 1) * GRID;
                while (*(volatile unsigned*)&g_cnt < tgt) { }
                __threadfence();
            }
            __syncwarp();
#pragma unroll
            for (int i = 0; i < HD / 4 / 32; i++) {
                int idx = i * 32 + lane;
                ((float4*)hS)[idx] = __ldcg((const float4*)g_hr + idx);
            }
        }
        __syncthreads();   // S2: hr staged

        if (comp) {
            // ---- candidate + new h ----
#pragma unroll
            for (int k = 0; k < 32; k++) hreg[k] = ((const float2*)hS)[k * 32 + lane];
            float cc0, cc1;
            dot2_h(wC0, wC1, hreg, lane, cc0, cc1);
            cc0 = tanhf(cc0 + pc.x);
            cc1 = tanhf(cc1 + pc.y);
            const float hn0 = cc0 * u0 + hold0 * (1.f - u0);
            const float hn1 = cc1 * u1 + hold1 * (1.f - u1);
            if (lane == 0)
                __stcg((float2*)&g_h[nxt][j0], make_float2(hn0, hn1));
        }
        __syncthreads();   // S3: h_new stores done; hS free for overwrite

        if (comp) {
            // ---- B2 shadow: prefetch pre[t+1] ----
            if (t + 1 < TT) {
                const float* pn = g_pre + (size_t)(t + 1) * (3 * HD);
                pu = __ldcg((const float2*)&pn[0 * HD + j0]);
                pr = __ldcg((const float2*)&pn[1 * HD + j0]);
                pc = __ldcg((const float2*)&pn[2 * HD + j0]);
            }
        } else {
            // ---- sync warp: B2 arrive, poll, stage s_{t+1} -> hS ----
            if (lane == 0) {
                __threadfence();
                atomicAdd(&g_cnt, 1u);
                unsigned tgt = (unsigned)(2 * t + 2) * GRID;
                while (*(volatile unsigned*)&g_cnt < tgt) { }
                __threadfence();
            }
            __syncwarp();
#pragma unroll
            for (int i = 0; i < HD / 4 / 32; i++) {
                int idx = i * 32 + lane;
                ((float4*)hS)[idx] = __ldcg((const float4*)g_h[nxt] + idx);
            }
        }
        __syncthreads();   // S4: s_{t+1} staged
    }

    // ---- epilogue: hS = s_TT. y[TT-1] and h_fin ----
    if (w < 2) {
#pragma unroll
        for (int k = 0; k < 32; k++) hreg[k] = ((const float2*)hS)[k * 32 + lane];
        float yv = dot_y(wy, hreg, lane) + yb;
        if (lane == 0) out[(size_t)(TT - 1) * YD + cta * 2 + w] = yv;
    }
    if (cta == 0 && out_size >= TT * YD + HD) {
        for (int i = tid; i < HD; i += NTH) out[(size_t)TT * YD + i] = hS[i];
    }
}

// ------------------------------------------------------------------
// Launch
// ------------------------------------------------------------------
extern "C" void kernel_launch(void* const* d_in, const int* in_sizes, int n_in,
                              void* d_out, int out_size) {
    const float* x   = (const float*)d_in[0];
    const float* h0  = (const float*)d_in[1];
    const float* Wc  = (const float*)d_in[2];
    const float* Wu  = (const float*)d_in[3];
    const float* Wr  = (const float*)d_in[4];
    const float* bc  = (const float*)d_in[5];
    const float* bu  = (const float*)d_in[6];
    const float* br  = (const float*)d_in[7];
    const float* Why = (const float*)d_in[8];
    const float* by  = (const float*)d_in[9];
    float* out = (float*)d_out;

    cudaFuncSetAttribute(gru_seq, cudaFuncAttributeMaxDynamicSharedMemorySize, SMEM_SEQ);

    init_kernel<<<8, 256>>>(h0);

    dim3 g(HD / 64, TT / 64, 3);
    pre_gemm<<<g, 256>>>(x, Wu, Wr, Wc, bu, br, bc);

    gru_seq<<<GRID, NTH, SMEM_SEQ>>>(Wu, Wr, Wc, Why, by, out, out_size);
}